// round 2
// baseline (speedup 1.0000x reference)
#include <cuda_runtime.h>

#define N_NODES 50000
#define N_EDGES 800000
#define IN_DIM 64
#define EDGE_DIM 32
#define OUT_DIM 64

// ---- scratch (static device globals: allocation-free) ----
__device__ int  g_deg[N_NODES];
__device__ int  g_start[N_NODES + 1];
__device__ int  g_cursor[N_NODES];
__device__ int2 g_adj[N_EDGES];          // (src, edge_id) packed per dst bucket
__device__ int  g_is64;                  // 1 if edge_index is int64, 0 if int32

// Detect dtype of edge_index: if int64 (all values < 2^31, nonneg), every odd
// 32-bit word of the raw buffer is 0. If int32 node ids, odd words are random
// ids in [0, N_NODES) -> virtually never all zero over 1024 samples.
__global__ void k_detect(const int* __restrict__ ei32) {
    __shared__ int nz;
    if (threadIdx.x == 0) nz = 0;
    __syncthreads();
    int v = ei32[2 * threadIdx.x + 1];
    if (v != 0) atomicAdd(&nz, 1);
    __syncthreads();
    if (threadIdx.x == 0) g_is64 = (nz == 0) ? 1 : 0;
}

__device__ __forceinline__ int load_idx(const void* ei, int pos) {
    int v;
    if (g_is64) v = (int)((const long long*)ei)[pos];
    else        v = ((const int*)ei)[pos];
    // clamp: a mis-parse becomes a rel_err failure, not an addr-space fault
    return min(max(v, 0), N_NODES - 1);
}

__global__ void k_zero_deg() {
    int i = blockIdx.x * blockDim.x + threadIdx.x;
    if (i < N_NODES) g_deg[i] = 0;
}

__global__ void k_count(const void* __restrict__ ei) {
    int e = blockIdx.x * blockDim.x + threadIdx.x;
    if (e < N_EDGES) {
        int dst = load_idx(ei, N_EDGES + e);
        atomicAdd(&g_deg[dst], 1);       // no return use -> RED
    }
}

// single-block exclusive scan over 50000 degrees -> CSR offsets + cursors
__global__ void k_scan() {
    __shared__ int ssum[1024];
    const int t  = threadIdx.x;
    const int CH = (N_NODES + 1023) / 1024;   // 49
    int base = t * CH;
    int lim  = min(base + CH, N_NODES);
    int s = 0;
    for (int i = base; i < lim; ++i) s += g_deg[i];
    ssum[t] = s;
    __syncthreads();
    // Hillis-Steele inclusive scan
    for (int off = 1; off < 1024; off <<= 1) {
        int v = (t >= off) ? ssum[t - off] : 0;
        __syncthreads();
        ssum[t] += v;
        __syncthreads();
    }
    int run = ssum[t] - s;               // exclusive prefix for this chunk
    for (int i = base; i < lim; ++i) {
        int d = g_deg[i];
        g_start[i]  = run;
        g_cursor[i] = run;
        run += d;
    }
    if (t == 0) g_start[N_NODES] = N_EDGES;
}

__global__ void k_scatter(const void* __restrict__ ei) {
    int e = blockIdx.x * blockDim.x + threadIdx.x;
    if (e < N_EDGES) {
        int src = load_idx(ei, e);
        int dst = load_idx(ei, N_EDGES + e);
        int pos = atomicAdd(&g_cursor[dst], 1);
        pos = min(max(pos, 0), N_EDGES - 1);
        g_adj[pos] = make_int2(src, e);
    }
}

// One warp owns 4 nodes. Register-resident segment sums, then fused
// out = x@self_w + self_b + (S1@W1 + S2@W2)/deg + msg_b*[deg>0]
// via shuffle-broadcast GEMM with weights in shared memory.
__global__ void __launch_bounds__(256) k_aggregate(
    const float* __restrict__ x,
    const float* __restrict__ ea,
    const float* __restrict__ msg_w,     // [96,64] rows 0:64 = W1 (x part), 64:96 = W2 (edge part)
    const float* __restrict__ msg_b,
    const float* __restrict__ self_w,    // [64,64]
    const float* __restrict__ self_b,
    float* __restrict__ out)
{
    __shared__ float s_self[IN_DIM * OUT_DIM];                 // 16 KB
    __shared__ float s_msg[(IN_DIM + EDGE_DIM) * OUT_DIM];     // 24 KB

    const int tid = threadIdx.x;
    for (int i = tid; i < IN_DIM * OUT_DIM; i += 256)              s_self[i] = self_w[i];
    for (int i = tid; i < (IN_DIM + EDGE_DIM) * OUT_DIM; i += 256) s_msg[i] = msg_w[i];
    __syncthreads();

    const int lane  = tid & 31;
    const int warp  = tid >> 5;
    const int group = blockIdx.x * 8 + warp;   // 4 nodes per warp
    if (group * 4 >= N_NODES) return;
    const int node0 = group * 4;               // N_NODES % 4 == 0, no partial groups

    float s1a[4], s1b[4], s2v[4], xa[4], xb[4], degf[4];

    #pragma unroll
    for (int t = 0; t < 4; ++t) {
        const int node = node0 + t;
        const int beg = g_start[node];
        const int end = g_start[node + 1];
        float a = 0.f, b = 0.f, c = 0.f;
        #pragma unroll 4
        for (int p = beg; p < end; ++p) {
            int2 aep = g_adj[p];
            float2 xv = *reinterpret_cast<const float2*>(x + (size_t)aep.x * IN_DIM + 2 * lane);
            a += xv.x;
            b += xv.y;
            c += ea[(size_t)aep.y * EDGE_DIM + lane];
        }
        const int d = end - beg;
        const float inv = 1.f / fmaxf((float)d, 1.f);
        s1a[t] = a * inv;
        s1b[t] = b * inv;
        s2v[t] = c * inv;
        degf[t] = (float)d;
        float2 xv = *reinterpret_cast<const float2*>(x + (size_t)node * IN_DIM + 2 * lane);
        xa[t] = xv.x;
        xb[t] = xv.y;
    }

    // epilogue: each lane produces output cols (lane, lane+32) for 4 nodes
    float m0[4], m1[4];
    const float bias0 = self_b[lane], bias1 = self_b[lane + 32];
    const float mb0   = msg_b[lane],  mb1   = msg_b[lane + 32];
    #pragma unroll
    for (int t = 0; t < 4; ++t) {
        m0[t] = bias0 + (degf[t] > 0.f ? mb0 : 0.f);
        m1[t] = bias1 + (degf[t] > 0.f ? mb1 : 0.f);
    }

    #pragma unroll
    for (int i = 0; i < 32; ++i) {
        // weight rows 2i, 2i+1 (self & msg-x part) and row i of edge part
        const float wS00 = s_self[(2 * i) * 64 + lane];
        const float wS01 = s_self[(2 * i) * 64 + lane + 32];
        const float wS10 = s_self[(2 * i + 1) * 64 + lane];
        const float wS11 = s_self[(2 * i + 1) * 64 + lane + 32];
        const float wM00 = s_msg[(2 * i) * 64 + lane];
        const float wM01 = s_msg[(2 * i) * 64 + lane + 32];
        const float wM10 = s_msg[(2 * i + 1) * 64 + lane];
        const float wM11 = s_msg[(2 * i + 1) * 64 + lane + 32];
        const float wE0  = s_msg[(64 + i) * 64 + lane];
        const float wE1  = s_msg[(64 + i) * 64 + lane + 32];
        #pragma unroll
        for (int t = 0; t < 4; ++t) {
            const float a = __shfl_sync(0xffffffffu, xa[t],  i);  // x[2i]
            const float b = __shfl_sync(0xffffffffu, xb[t],  i);  // x[2i+1]
            const float c = __shfl_sync(0xffffffffu, s1a[t], i);  // S1'[2i]
            const float d = __shfl_sync(0xffffffffu, s1b[t], i);  // S1'[2i+1]
            const float e = __shfl_sync(0xffffffffu, s2v[t], i);  // S2'[i]
            m0[t] += a * wS00 + b * wS10 + c * wM00 + d * wM10 + e * wE0;
            m1[t] += a * wS01 + b * wS11 + c * wM01 + d * wM11 + e * wE1;
        }
    }

    #pragma unroll
    for (int t = 0; t < 4; ++t) {
        const int node = node0 + t;
        out[(size_t)node * OUT_DIM + lane]      = m0[t];
        out[(size_t)node * OUT_DIM + lane + 32] = m1[t];
    }
}

extern "C" void kernel_launch(void* const* d_in, const int* in_sizes, int n_in,
                              void* d_out, int out_size) {
    // Identify inputs by element count (robust to metadata ordering):
    //   x=3,200,000  edge_index=1,600,000  edge_attr=25,600,000
    //   msg_w=6,144  self_w=4,096  msg_b/self_b=64 (msg_b first)
    const float* x = 0; const void* ei = 0; const float* ea = 0;
    const float* msg_w = 0; const float* self_w = 0;
    const float* msg_b = 0; const float* self_b = 0;
    for (int i = 0; i < n_in; ++i) {
        const int sz = in_sizes[i];
        if      (sz == N_NODES * IN_DIM)             x      = (const float*)d_in[i];
        else if (sz == 2 * N_EDGES)                  ei     = d_in[i];
        else if (sz == N_EDGES * EDGE_DIM)           ea     = (const float*)d_in[i];
        else if (sz == (IN_DIM + EDGE_DIM) * OUT_DIM) msg_w = (const float*)d_in[i];
        else if (sz == IN_DIM * OUT_DIM)             self_w = (const float*)d_in[i];
        else if (sz == OUT_DIM) {
            if (!msg_b) msg_b = (const float*)d_in[i];
            else        self_b = (const float*)d_in[i];
        }
    }
    float* out = (float*)d_out;

    k_detect<<<1, 1024>>>((const int*)ei);
    k_zero_deg<<<(N_NODES + 255) / 256, 256>>>();
    k_count<<<(N_EDGES + 255) / 256, 256>>>(ei);
    k_scan<<<1, 1024>>>();
    k_scatter<<<(N_EDGES + 255) / 256, 256>>>(ei);

    const int groups = (N_NODES + 3) / 4;          // 12500 warps
    const int blocks = (groups + 7) / 8;           // 8 warps/block
    k_aggregate<<<blocks, 256>>>(x, ea, msg_w, msg_b, self_w, self_b, out);
}

// round 3
// speedup vs baseline: 1.4921x; 1.4921x over previous
#include <cuda_runtime.h>

#define N_NODES 50000
#define N_EDGES 800000
#define IN_DIM 64
#define EDGE_DIM 32
#define OUT_DIM 64

// ---- scratch (static device globals: allocation-free) ----
__device__ int  g_deg[N_NODES];
__device__ int  g_start[N_NODES];
__device__ int  g_cursor[N_NODES];
__device__ int  g_total;
__device__ int2 g_adj[N_EDGES];          // (src, edge_id) packed per dst bucket
__device__ int  g_is64;                  // 1 if edge_index is int64, 0 if int32

// Detect dtype of edge_index: if int64 (values < 2^31, nonneg), every odd
// 32-bit word of the raw buffer is 0. If int32 node ids, odd words are random
// ids in [0, N_NODES) -> virtually never all zero over 1024 samples.
__global__ void k_detect(const int* __restrict__ ei32) {
    __shared__ int nz;
    if (threadIdx.x == 0) nz = 0;
    __syncthreads();
    int v = ei32[2 * threadIdx.x + 1];
    if (v != 0) atomicAdd(&nz, 1);
    __syncthreads();
    if (threadIdx.x == 0) g_is64 = (nz == 0) ? 1 : 0;
}

__device__ __forceinline__ int load_idx(const void* ei, int pos) {
    int v;
    if (g_is64) v = (int)((const long long*)ei)[pos];
    else        v = ((const int*)ei)[pos];
    return min(max(v, 0), N_NODES - 1);   // mis-parse -> rel_err fail, not fault
}

__global__ void k_zero_deg() {
    int i = blockIdx.x * blockDim.x + threadIdx.x;
    if (i < N_NODES) g_deg[i] = 0;
    if (i == 0) g_total = 0;
}

__global__ void k_count(const void* __restrict__ ei) {
    int e = blockIdx.x * blockDim.x + threadIdx.x;
    if (e < N_EDGES) {
        int dst = load_idx(ei, N_EDGES + e);
        atomicAdd(&g_deg[dst], 1);       // no return use -> RED
    }
}

// Unordered segment allocator: segments need only be contiguous per node,
// NOT in node order. Warp shuffle-scan of 32 degrees + one atomicAdd/warp.
__global__ void k_alloc() {
    const int i    = blockIdx.x * blockDim.x + threadIdx.x;
    const int lane = threadIdx.x & 31;
    int d = (i < N_NODES) ? g_deg[i] : 0;
    int s = d;
    #pragma unroll
    for (int off = 1; off < 32; off <<= 1) {
        int v = __shfl_up_sync(0xffffffffu, s, off);
        if (lane >= off) s += v;
    }
    const int excl  = s - d;                      // exclusive prefix in warp
    const int total = __shfl_sync(0xffffffffu, s, 31);
    int base = 0;
    if (lane == 31) base = atomicAdd(&g_total, total);
    base = __shfl_sync(0xffffffffu, base, 31);
    if (i < N_NODES) {
        g_start[i]  = base + excl;
        g_cursor[i] = base + excl;
    }
}

__global__ void k_scatter(const void* __restrict__ ei) {
    int e = blockIdx.x * blockDim.x + threadIdx.x;
    if (e < N_EDGES) {
        int src = load_idx(ei, e);
        int dst = load_idx(ei, N_EDGES + e);
        int pos = atomicAdd(&g_cursor[dst], 1);
        pos = min(max(pos, 0), N_EDGES - 1);
        g_adj[pos] = make_int2(src, e);
    }
}

// One warp owns 4 nodes. Register-resident segment sums, then fused
// out = x@self_w + self_b + (S1@W1 + S2@W2)/deg + msg_b*[deg>0]
// via shuffle-broadcast GEMM with weights in shared memory.
__global__ void __launch_bounds__(256) k_aggregate(
    const float* __restrict__ x,
    const float* __restrict__ ea,
    const float* __restrict__ msg_w,     // [96,64] rows 0:64 = W1 (x part), 64:96 = W2 (edge part)
    const float* __restrict__ msg_b,
    const float* __restrict__ self_w,    // [64,64]
    const float* __restrict__ self_b,
    float* __restrict__ out)
{
    __shared__ float s_self[IN_DIM * OUT_DIM];                 // 16 KB
    __shared__ float s_msg[(IN_DIM + EDGE_DIM) * OUT_DIM];     // 24 KB

    const int tid = threadIdx.x;
    for (int i = tid; i < IN_DIM * OUT_DIM; i += 256)              s_self[i] = self_w[i];
    for (int i = tid; i < (IN_DIM + EDGE_DIM) * OUT_DIM; i += 256) s_msg[i] = msg_w[i];
    __syncthreads();

    const int lane  = tid & 31;
    const int warp  = tid >> 5;
    const int group = blockIdx.x * 8 + warp;   // 4 nodes per warp
    if (group * 4 >= N_NODES) return;
    const int node0 = group * 4;               // N_NODES % 4 == 0, no partial groups

    float s1a[4], s1b[4], s2v[4], xa[4], xb[4], degf[4];

    #pragma unroll
    for (int t = 0; t < 4; ++t) {
        const int node = node0 + t;
        const int beg = g_start[node];
        const int d   = g_deg[node];
        const int end = beg + d;
        float a = 0.f, b = 0.f, c = 0.f;
        #pragma unroll 4
        for (int p = beg; p < end; ++p) {
            int2 aep = g_adj[p];
            float2 xv = *reinterpret_cast<const float2*>(x + (size_t)aep.x * IN_DIM + 2 * lane);
            a += xv.x;
            b += xv.y;
            c += ea[(size_t)aep.y * EDGE_DIM + lane];
        }
        const float inv = 1.f / fmaxf((float)d, 1.f);
        s1a[t] = a * inv;
        s1b[t] = b * inv;
        s2v[t] = c * inv;
        degf[t] = (float)d;
        float2 xv = *reinterpret_cast<const float2*>(x + (size_t)node * IN_DIM + 2 * lane);
        xa[t] = xv.x;
        xb[t] = xv.y;
    }

    // epilogue: each lane produces output cols (lane, lane+32) for 4 nodes
    float m0[4], m1[4];
    const float bias0 = self_b[lane], bias1 = self_b[lane + 32];
    const float mb0   = msg_b[lane],  mb1   = msg_b[lane + 32];
    #pragma unroll
    for (int t = 0; t < 4; ++t) {
        m0[t] = bias0 + (degf[t] > 0.f ? mb0 : 0.f);
        m1[t] = bias1 + (degf[t] > 0.f ? mb1 : 0.f);
    }

    #pragma unroll
    for (int i = 0; i < 32; ++i) {
        const float wS00 = s_self[(2 * i) * 64 + lane];
        const float wS01 = s_self[(2 * i) * 64 + lane + 32];
        const float wS10 = s_self[(2 * i + 1) * 64 + lane];
        const float wS11 = s_self[(2 * i + 1) * 64 + lane + 32];
        const float wM00 = s_msg[(2 * i) * 64 + lane];
        const float wM01 = s_msg[(2 * i) * 64 + lane + 32];
        const float wM10 = s_msg[(2 * i + 1) * 64 + lane];
        const float wM11 = s_msg[(2 * i + 1) * 64 + lane + 32];
        const float wE0  = s_msg[(64 + i) * 64 + lane];
        const float wE1  = s_msg[(64 + i) * 64 + lane + 32];
        #pragma unroll
        for (int t = 0; t < 4; ++t) {
            const float a = __shfl_sync(0xffffffffu, xa[t],  i);  // x[2i]
            const float b = __shfl_sync(0xffffffffu, xb[t],  i);  // x[2i+1]
            const float c = __shfl_sync(0xffffffffu, s1a[t], i);  // S1'[2i]
            const float d = __shfl_sync(0xffffffffu, s1b[t], i);  // S1'[2i+1]
            const float e = __shfl_sync(0xffffffffu, s2v[t], i);  // S2'[i]
            m0[t] += a * wS00 + b * wS10 + c * wM00 + d * wM10 + e * wE0;
            m1[t] += a * wS01 + b * wS11 + c * wM01 + d * wM11 + e * wE1;
        }
    }

    #pragma unroll
    for (int t = 0; t < 4; ++t) {
        const int node = node0 + t;
        out[(size_t)node * OUT_DIM + lane]      = m0[t];
        out[(size_t)node * OUT_DIM + lane + 32] = m1[t];
    }
}

extern "C" void kernel_launch(void* const* d_in, const int* in_sizes, int n_in,
                              void* d_out, int out_size) {
    // Identify inputs by element count (robust to metadata ordering):
    //   x=3,200,000  edge_index=1,600,000  edge_attr=25,600,000
    //   msg_w=6,144  self_w=4,096  msg_b/self_b=64 (msg_b first)
    const float* x = 0; const void* ei = 0; const float* ea = 0;
    const float* msg_w = 0; const float* self_w = 0;
    const float* msg_b = 0; const float* self_b = 0;
    for (int i = 0; i < n_in; ++i) {
        const int sz = in_sizes[i];
        if      (sz == N_NODES * IN_DIM)              x      = (const float*)d_in[i];
        else if (sz == 2 * N_EDGES)                   ei     = d_in[i];
        else if (sz == N_EDGES * EDGE_DIM)            ea     = (const float*)d_in[i];
        else if (sz == (IN_DIM + EDGE_DIM) * OUT_DIM) msg_w  = (const float*)d_in[i];
        else if (sz == IN_DIM * OUT_DIM)              self_w = (const float*)d_in[i];
        else if (sz == OUT_DIM) {
            if (!msg_b) msg_b = (const float*)d_in[i];
            else        self_b = (const float*)d_in[i];
        }
    }
    float* out = (float*)d_out;

    k_detect<<<1, 1024>>>((const int*)ei);
    k_zero_deg<<<(N_NODES + 255) / 256, 256>>>();
    k_count<<<(N_EDGES + 255) / 256, 256>>>(ei);
    k_alloc<<<(N_NODES + 255) / 256, 256>>>();
    k_scatter<<<(N_EDGES + 255) / 256, 256>>>(ei);

    const int groups = (N_NODES + 3) / 4;          // 12500 warps
    const int blocks = (groups + 7) / 8;           // 8 warps/block
    k_aggregate<<<blocks, 256>>>(x, ea, msg_w, msg_b, self_w, self_b, out);
}